// round 15
// baseline (speedup 1.0000x reference)
#include <cuda_runtime.h>
#include <cuda_fp16.h>
#include <cstdint>
#include <cstddef>

// ============================ problem dims ============================
static constexpr int E_   = 16;
static constexpr int NTOK = 2048;
static constexpr int DIM  = 1024;
static constexpr int HID  = 4096;

// ============================ scratch (device globals; no allocation) ============================
__device__ __align__(1024) __half g_xh [(size_t)E_ * NTOK * DIM];
__device__ __align__(1024) __half g_w1h[(size_t)E_ * HID  * DIM];   // [E][H][D] K-major
__device__ __align__(1024) __half g_w2h[(size_t)E_ * DIM  * HID];   // [E][D][H] K-major
__device__ __align__(1024) __half g_h  [(size_t)E_ * NTOK * HID];   // hidden fp16

// ============================ helpers ============================
#define DEVINL __device__ __forceinline__

DEVINL uint32_t smem_u32(const void* p) {
    uint32_t a;
    asm("{ .reg .u64 t; cvta.to.shared.u64 t, %1; cvt.u32.u64 %0, t; }" : "=r"(a) : "l"(p));
    return a;
}

// cp.async 16B
DEVINL void cp_async16(uint32_t smem_addr, const void* gptr) {
    asm volatile("cp.async.cg.shared.global [%0], [%1], 16;" :: "r"(smem_addr), "l"(gptr));
}
DEVINL void cp_commit() { asm volatile("cp.async.commit_group;" ::: "memory"); }
template <int N> DEVINL void cp_wait() { asm volatile("cp.async.wait_group %0;" :: "n"(N) : "memory"); }

DEVINL void ldsm_x4(uint32_t* r, uint32_t addr) {
    asm volatile("ldmatrix.sync.aligned.m8n8.x4.shared.b16 {%0,%1,%2,%3}, [%4];"
                 : "=r"(r[0]), "=r"(r[1]), "=r"(r[2]), "=r"(r[3]) : "r"(addr));
}

DEVINL void mma_fp16(float* c, const uint32_t* a, uint32_t b0, uint32_t b1) {
    asm volatile(
        "mma.sync.aligned.m16n8k16.row.col.f32.f16.f16.f32 "
        "{%0,%1,%2,%3}, {%4,%5,%6,%7}, {%8,%9}, {%0,%1,%2,%3};"
        : "+f"(c[0]), "+f"(c[1]), "+f"(c[2]), "+f"(c[3])
        : "r"(a[0]), "r"(a[1]), "r"(a[2]), "r"(a[3]), "r"(b0), "r"(b1));
}

// ============================ numeric helpers ============================
DEVINL float gelu_exact(float x) {
    return 0.5f * x * (1.0f + erff(x * 0.7071067811865476f));
}

// ============================ prep kernels ============================
__global__ void convert_x_kernel(const float* __restrict__ in,
                                 __half* __restrict__ outH, size_t n4) {
    size_t i = (size_t)blockIdx.x * blockDim.x + threadIdx.x;
    size_t stride = (size_t)gridDim.x * blockDim.x;
    for (; i < n4; i += stride) {
        float4 v = reinterpret_cast<const float4*>(in)[i];
        __half2 h0 = __floats2half2_rn(v.x, v.y);
        __half2 h1 = __floats2half2_rn(v.z, v.w);
        reinterpret_cast<uint2*>(outH)[i] =
            make_uint2(*reinterpret_cast<uint32_t*>(&h0), *reinterpret_cast<uint32_t*>(&h1));
    }
}

// transpose [E][R][C] fp32 -> [E][C][R] fp16
__global__ void transpose_half_kernel(const float* __restrict__ in,
                                      __half* __restrict__ outH,
                                      int R, int C) {
    __shared__ float tile[32][33];
    const int e = blockIdx.z;
    const float* inp = in + (size_t)e * R * C;
    __half* ph = outH + (size_t)e * R * C;
    const int c0 = blockIdx.x * 32;
    const int r0 = blockIdx.y * 32;
    const int tx = threadIdx.x, ty = threadIdx.y;
#pragma unroll
    for (int j = 0; j < 32; j += 8)
        tile[ty + j][tx] = inp[(size_t)(r0 + ty + j) * C + c0 + tx];
    __syncthreads();
#pragma unroll
    for (int j = 0; j < 32; j += 8) {
        float v = tile[tx][ty + j];
        size_t o = (size_t)(c0 + ty + j) * R + r0 + tx;
        ph[o] = __float2half(v);
    }
}

// ============================ GEMM kernel (single-pass fp16 mma.sync) ============================
// C[m][n] = A[m][k] * B[n][k]   (A row-major K-contig fp16, B [n][k] K-contig fp16)
// CTA tile 128x128, warp tile 32x64 (8 warps, 4Mx2N), BK=64, 3-stage cp.async,
// one barrier per k-iter, 2 CTAs/SM.
static constexpr int BM = 128, BN = 128, BK = 64, STAGES = 3;
static constexpr int ROW_B  = 144;                  // 128B data + 16B pad (16B-aligned, conflict-free)
static constexpr int ATILE_B = BM * ROW_B;          // 18432 B
static constexpr int BTILE_B = BN * ROW_B;          // 18432 B
static constexpr int OFF_A = 0;
static constexpr int OFF_B = ATILE_B;
static constexpr int STAGE_B = ATILE_B + BTILE_B;   // 36864 B
static constexpr int SMEM_DYN = STAGES * STAGE_B;   // 110592 B

template <bool GELU_OUT, int K, int NB>
__global__ __launch_bounds__(256, 2)
void ffn_gemm(const __half* __restrict__ A, const __half* __restrict__ B,
              const float* __restrict__ bias,
              float* __restrict__ outF, __half* __restrict__ outH) {
    extern __shared__ char smem[];
    const uint32_t sbase = smem_u32(smem);
    const int tid  = threadIdx.x;
    const int warp = tid >> 5;
    const int lane = tid & 31;

    const int e  = blockIdx.z;
    const int m0 = blockIdx.y * BM;
    const int n0 = blockIdx.x * BN;

    // loader: 2048 16B-chunks per stage (A 1024 + B 1024), 8 per thread
    const int lrow = tid >> 3;          // 0..31
    const int lcol = tid & 7;           // 0..7
    // hoisted global pointers; advance by BK each stage load
    const __half* pA = A + ((size_t)e * NTOK + m0) * K + lcol * 8;
    const __half* pB = B + ((size_t)e * NB   + n0) * K + lcol * 8;
    const uint32_t sOffA = OFF_A + lrow * ROW_B + lcol * 16;
    const uint32_t sOffB = OFF_B + lrow * ROW_B + lcol * 16;

    auto load_stage = [&](int s) {
        const uint32_t sb = sbase + s * STAGE_B;
#pragma unroll
        for (int j = 0; j < 4; j++)
            cp_async16(sb + sOffA + j * 32 * ROW_B, pA + (size_t)(j * 32 + lrow) * K);
#pragma unroll
        for (int j = 0; j < 4; j++)
            cp_async16(sb + sOffB + j * 32 * ROW_B, pB + (size_t)(j * 32 + lrow) * K);
        pA += BK;
        pB += BK;
    };

    // warp tiling: 4(M) x 2(N); warp tile 32(M) x 64(N)
    const int wm = (warp & 3) * 32;
    const int wn = (warp >> 2) * 64;

    // hoisted ldmatrix per-thread base offsets (add sb + kk*32 in the loop)
    const int aRow = (lane & 15);
    const int aK   = ((lane >> 4) & 1) * 8;
    const int bRow = ((lane >> 4) & 1) * 8 + (lane & 7);
    const int bK   = ((lane >> 3) & 1) * 8;
    uint32_t aBase[2], bBase[4];
#pragma unroll
    for (int mt = 0; mt < 2; mt++)
        aBase[mt] = OFF_A + (uint32_t)((wm + mt * 16 + aRow) * ROW_B + aK * 2);
#pragma unroll
    for (int np = 0; np < 4; np++)
        bBase[np] = OFF_B + (uint32_t)((wn + np * 16 + bRow) * ROW_B + bK * 2);

    float acc[2][8][4];
#pragma unroll
    for (int mt = 0; mt < 2; mt++)
#pragma unroll
        for (int nt = 0; nt < 8; nt++)
#pragma unroll
            for (int i = 0; i < 4; i++) acc[mt][nt][i] = 0.0f;

    constexpr int nk = K / BK;

    // prologue: fill 2 of 3 stages
    load_stage(0); cp_commit();
    load_stage(1); cp_commit();

    for (int i = 0; i < nk; i++) {
        if (i + 1 < nk) cp_wait<1>(); else cp_wait<0>();
        __syncthreads();   // single barrier per iter:
                           //  - stage i data now visible to all warps
                           //  - all warps finished reading stage (i+2)%3 in iter i-1,
                           //    so the prefetch below may overwrite it
        if (i + 2 < nk) {
            load_stage((i + 2) % STAGES);
            cp_commit();
        }
        const uint32_t sb = sbase + (i % STAGES) * STAGE_B;

#pragma unroll
        for (int kk = 0; kk < 4; kk++) {
            const uint32_t ko = (uint32_t)(kk * 32);   // 16 elems * 2B per kk step
            uint32_t Af[2][4], Bf[4][4];
#pragma unroll
            for (int mt = 0; mt < 2; mt++)
                ldsm_x4(Af[mt], sb + aBase[mt] + ko);
#pragma unroll
            for (int np = 0; np < 4; np++)
                ldsm_x4(Bf[np], sb + bBase[np] + ko);
#pragma unroll
            for (int mt = 0; mt < 2; mt++)
#pragma unroll
                for (int np = 0; np < 4; np++) {
                    mma_fp16(acc[mt][np * 2 + 0], Af[mt], Bf[np][0], Bf[np][1]);
                    mma_fp16(acc[mt][np * 2 + 1], Af[mt], Bf[np][2], Bf[np][3]);
                }
        }
    }

    // ============================ epilogue ============================
#pragma unroll
    for (int mt = 0; mt < 2; mt++) {
#pragma unroll
        for (int nt = 0; nt < 8; nt++) {
            const int n = n0 + wn + nt * 8 + (lane & 3) * 2;
            const float b0 = bias[n], b1 = bias[n + 1];
#pragma unroll
            for (int half = 0; half < 2; half++) {
                const int m = m0 + wm + mt * 16 + (lane >> 2) + half * 8;
                float v0 = acc[mt][nt][half * 2 + 0] + b0;
                float v1 = acc[mt][nt][half * 2 + 1] + b1;
                const size_t o = ((size_t)e * NTOK + m) * NB + n;
                if constexpr (GELU_OUT) {
                    v0 = gelu_exact(v0);
                    v1 = gelu_exact(v1);
                    __half2 h = __floats2half2_rn(v0, v1);
                    *reinterpret_cast<uint32_t*>(outH + o) = *reinterpret_cast<uint32_t*>(&h);
                } else {
                    *reinterpret_cast<float2*>(outF + o) = make_float2(v0, v1);
                }
            }
        }
    }
}

// ============================ host launch ============================
extern "C" void kernel_launch(void* const* d_in, const int* in_sizes, int n_in,
                              void* d_out, int out_size) {
    (void)in_sizes; (void)n_in; (void)out_size;
    const float* x  = (const float*)d_in[0];
    const float* w1 = (const float*)d_in[1];
    const float* w2 = (const float*)d_in[2];
    const float* b1 = (const float*)d_in[3];
    const float* b2 = (const float*)d_in[4];
    float* out = (float*)d_out;

    void *xh, *w1h, *w2h, *hh;
    cudaGetSymbolAddress(&xh,  g_xh);
    cudaGetSymbolAddress(&w1h, g_w1h);
    cudaGetSymbolAddress(&w2h, g_w2h);
    cudaGetSymbolAddress(&hh,  g_h);

    cudaFuncSetAttribute(ffn_gemm<true,  DIM, HID>,
                         cudaFuncAttributeMaxDynamicSharedMemorySize, SMEM_DYN);
    cudaFuncSetAttribute(ffn_gemm<false, HID, DIM>,
                         cudaFuncAttributeMaxDynamicSharedMemorySize, SMEM_DYN);

    // 1) convert x -> fp16
    const size_t n4 = (size_t)E_ * NTOK * DIM / 4;
    convert_x_kernel<<<8192, 256>>>(x, (__half*)xh, n4);

    // 2) transpose weights -> K-major fp16
    transpose_half_kernel<<<dim3(HID / 32, DIM / 32, E_), dim3(32, 8)>>>(
        w1, (__half*)w1h, DIM, HID);
    transpose_half_kernel<<<dim3(DIM / 32, HID / 32, E_), dim3(32, 8)>>>(
        w2, (__half*)w2h, HID, DIM);

    // 3) GEMM1: hidden = gelu(x @ w1 + b1) -> fp16
    ffn_gemm<true, DIM, HID><<<dim3(HID / BN, NTOK / BM, E_), 256, SMEM_DYN>>>(
        (const __half*)xh, (const __half*)w1h, b1, nullptr, (__half*)hh);

    // 4) GEMM2: out = hidden @ w2 + b2 -> fp32
    ffn_gemm<false, HID, DIM><<<dim3(DIM / BN, NTOK / BM, E_), 256, SMEM_DYN>>>(
        (const __half*)hh, (const __half*)w2h, b2, out, nullptr);
}